// round 5
// baseline (speedup 1.0000x reference)
#include <cuda_runtime.h>
#include <math.h>

// Shapes (fixed per problem)
#define B_DIM 4096
#define IN_DIM 1024
#define H_DIM 2048
#define A_DIM 64
#define A2_DIM 4096   // A*A

// Scratch (allocation-free rule: __device__ globals)
__device__ float g_x [B_DIM * H_DIM];        // fc1 output (post-relu)
__device__ float g_gi[B_DIM * 3 * H_DIM];    // x @ Wih^T + bih
__device__ float g_gh[B_DIM * 3 * H_DIM];    // h_in @ Whh^T + bhh
__device__ float g_h [B_DIM * H_DIM];        // new hidden state
__device__ float g_q [B_DIM * A2_DIM];       // fc2 output

// ---------------------------------------------------------------------------
// SIMT fp32 GEMM: C[M,N] = A[M,K] @ Bw[N,K]^T + bias[N], optional ReLU.
// Block tile 128x128, K-tile 16, 256 threads, 8x8 per-thread (split 4+4
// in both dims for conflict-free float4 shared loads).
// All dims are multiples of the tiles -> no bounds checks.
// ---------------------------------------------------------------------------
#define BM 128
#define BN 128
#define BK 16

template<int ACT>
__global__ __launch_bounds__(256, 2)
void sgemm_bias_act(const float* __restrict__ A,
                    const float* __restrict__ Bw,
                    const float* __restrict__ bias,
                    float* __restrict__ C,
                    int K, int N)
{
    __shared__ float As[BK][BM + 4];
    __shared__ float Bs[BK][BN + 4];

    const int tid = threadIdx.x;
    const int bm  = blockIdx.y * BM;
    const int bn  = blockIdx.x * BN;

    // global -> smem loader mapping (2 float4 per operand per thread)
    const int ldr  = tid >> 2;          // 0..63
    const int ldc  = (tid & 3) << 2;    // 0,4,8,12

    // compute mapping: 8 warps as 4(M) x 2(N); lanes as 4(M) x 8(N)
    const int lane = tid & 31;
    const int warp = tid >> 5;
    const int wm   = (warp & 3) * 32;
    const int wn   = (warp >> 2) * 64;
    const int row0 = wm + ((lane >> 3) << 2);   // +16 for second half
    const int col0 = wn + ((lane & 7) << 2);    // +32 for second half

    float acc[2][2][4][4];
    #pragma unroll
    for (int a = 0; a < 2; a++)
        #pragma unroll
        for (int b = 0; b < 2; b++)
            #pragma unroll
            for (int i = 0; i < 4; i++)
                #pragma unroll
                for (int j = 0; j < 4; j++)
                    acc[a][b][i][j] = 0.0f;

    const float* Ap = A  + (size_t)bm * K;
    const float* Bp = Bw + (size_t)bn * K;

    for (int k0 = 0; k0 < K; k0 += BK) {
        #pragma unroll
        for (int r = 0; r < 2; r++) {
            const int rr = ldr + r * 64;
            float4 v = *reinterpret_cast<const float4*>(Ap + (size_t)rr * K + k0 + ldc);
            As[ldc + 0][rr] = v.x;
            As[ldc + 1][rr] = v.y;
            As[ldc + 2][rr] = v.z;
            As[ldc + 3][rr] = v.w;
            float4 w = *reinterpret_cast<const float4*>(Bp + (size_t)rr * K + k0 + ldc);
            Bs[ldc + 0][rr] = w.x;
            Bs[ldc + 1][rr] = w.y;
            Bs[ldc + 2][rr] = w.z;
            Bs[ldc + 3][rr] = w.w;
        }
        __syncthreads();

        #pragma unroll
        for (int kk = 0; kk < BK; kk++) {
            float a0[4], a1[4], b0[4], b1[4];
            *reinterpret_cast<float4*>(a0) = *reinterpret_cast<const float4*>(&As[kk][row0]);
            *reinterpret_cast<float4*>(a1) = *reinterpret_cast<const float4*>(&As[kk][row0 + 16]);
            *reinterpret_cast<float4*>(b0) = *reinterpret_cast<const float4*>(&Bs[kk][col0]);
            *reinterpret_cast<float4*>(b1) = *reinterpret_cast<const float4*>(&Bs[kk][col0 + 32]);
            #pragma unroll
            for (int i = 0; i < 4; i++) {
                #pragma unroll
                for (int j = 0; j < 4; j++) {
                    acc[0][0][i][j] += a0[i] * b0[j];
                    acc[0][1][i][j] += a0[i] * b1[j];
                    acc[1][0][i][j] += a1[i] * b0[j];
                    acc[1][1][i][j] += a1[i] * b1[j];
                }
            }
        }
        __syncthreads();
    }

    // epilogue: bias (+relu), vectorized, coalesced
    #pragma unroll
    for (int mh = 0; mh < 2; mh++) {
        #pragma unroll
        for (int i = 0; i < 4; i++) {
            const int r = bm + row0 + mh * 16 + i;
            #pragma unroll
            for (int nh = 0; nh < 2; nh++) {
                const int c = bn + col0 + nh * 32;
                float4 bv = *reinterpret_cast<const float4*>(bias + c);
                float4 v;
                v.x = acc[mh][nh][i][0] + bv.x;
                v.y = acc[mh][nh][i][1] + bv.y;
                v.z = acc[mh][nh][i][2] + bv.z;
                v.w = acc[mh][nh][i][3] + bv.w;
                if (ACT == 1) {
                    v.x = fmaxf(v.x, 0.0f);
                    v.y = fmaxf(v.y, 0.0f);
                    v.z = fmaxf(v.z, 0.0f);
                    v.w = fmaxf(v.w, 0.0f);
                }
                *reinterpret_cast<float4*>(C + (size_t)r * N + c) = v;
            }
        }
    }
}

// ---------------------------------------------------------------------------
// GRU elementwise: r/z/n gates from g_gi, g_gh (biases already folded in),
// h = (1-z)*n + z*h_in. Writes both scratch g_h and the h-region of d_out.
// ---------------------------------------------------------------------------
__global__ void gru_kernel(const float* __restrict__ hin,
                           float* __restrict__ hout)
{
    const int idx = blockIdx.x * 256 + threadIdx.x;   // b*H + i
    const int b = idx >> 11;
    const int i = idx & (H_DIM - 1);
    const float* gib = g_gi + (size_t)b * (3 * H_DIM);
    const float* ghb = g_gh + (size_t)b * (3 * H_DIM);

    const float r = 1.0f / (1.0f + expf(-(gib[i] + ghb[i])));
    const float z = 1.0f / (1.0f + expf(-(gib[H_DIM + i] + ghb[H_DIM + i])));
    const float n = tanhf(gib[2 * H_DIM + i] + r * ghb[2 * H_DIM + i]);
    const float hv = (1.0f - z) * n + z * hin[idx];

    g_h[idx]  = hv;
    hout[idx] = hv;
}

// ---------------------------------------------------------------------------
// Decode: per batch row b of q[4096]:
//   out[2b,   j] = max_{k<64} q[j + k]                 (contiguous window)
//   out[2b+1, j] = max_{k<64} q[(j + 64k - 1) mod 4096] (strided, wrap)
// One block per row; stage the row in smem.
// ---------------------------------------------------------------------------
__global__ void decode_kernel(float* __restrict__ out)
{
    __shared__ float s[A2_DIM];
    const int b = blockIdx.x;
    const float* qr = g_q + (size_t)b * A2_DIM;
    for (int i = threadIdx.x; i < A2_DIM; i += 256) s[i] = qr[i];
    __syncthreads();

    const int t = threadIdx.x;
    if (t < A_DIM) {
        float m = -3.402823466e38f;
        #pragma unroll 8
        for (int k = 0; k < A_DIM; k++) m = fmaxf(m, s[t + k]);
        out[(size_t)(2 * b) * A_DIM + t] = m;
    } else if (t < 2 * A_DIM) {
        const int j = t - A_DIM;
        float m = -3.402823466e38f;
        #pragma unroll 8
        for (int k = 0; k < A_DIM; k++)
            m = fmaxf(m, s[(j + A_DIM * k + (A2_DIM - 1)) & (A2_DIM - 1)]);
        out[(size_t)(2 * b + 1) * A_DIM + j] = m;
    }
}

// ---------------------------------------------------------------------------
// Launch: inputs, hidden_state, W1, b1, Wih, Whh, bih, bhh, W2, b2
// Output layout assumed: decode rows [2B, A] first (524288 floats),
// then h [B, H] (8388608 floats).
// ---------------------------------------------------------------------------
extern "C" void kernel_launch(void* const* d_in, const int* in_sizes, int n_in,
                              void* d_out, int out_size)
{
    const float* inputs = (const float*)d_in[0];
    const float* hidden = (const float*)d_in[1];
    const float* W1  = (const float*)d_in[2];
    const float* b1  = (const float*)d_in[3];
    const float* Wih = (const float*)d_in[4];
    const float* Whh = (const float*)d_in[5];
    const float* bih = (const float*)d_in[6];
    const float* bhh = (const float*)d_in[7];
    const float* W2  = (const float*)d_in[8];
    const float* b2  = (const float*)d_in[9];
    float* out = (float*)d_out;

    void *px, *pgi, *pgh, *ph, *pq;
    cudaGetSymbolAddress(&px,  g_x);
    cudaGetSymbolAddress(&pgi, g_gi);
    cudaGetSymbolAddress(&pgh, g_gh);
    cudaGetSymbolAddress(&ph,  g_h);
    cudaGetSymbolAddress(&pq,  g_q);

    const dim3 blk(256);

    // fc1 + relu: x = relu(inputs @ W1^T + b1)
    sgemm_bias_act<1><<<dim3(H_DIM / BN, B_DIM / BM), blk>>>(
        inputs, W1, b1, (float*)px, IN_DIM, H_DIM);

    // gi = x @ Wih^T + bih
    sgemm_bias_act<0><<<dim3(3 * H_DIM / BN, B_DIM / BM), blk>>>(
        (const float*)px, Wih, bih, (float*)pgi, H_DIM, 3 * H_DIM);

    // gh = h_in @ Whh^T + bhh
    sgemm_bias_act<0><<<dim3(3 * H_DIM / BN, B_DIM / BM), blk>>>(
        hidden, Whh, bhh, (float*)pgh, H_DIM, 3 * H_DIM);

    // GRU elementwise -> g_h and d_out h-region
    gru_kernel<<<B_DIM * H_DIM / 256, 256>>>(hidden, out + (size_t)2 * B_DIM * A_DIM);

    // q = h @ W2^T + b2
    sgemm_bias_act<0><<<dim3(A2_DIM / BN, B_DIM / BM), blk>>>(
        (const float*)ph, W2, b2, (float*)pq, H_DIM, A2_DIM);

    // windowed-max decode -> d_out[0 .. 2B*A)
    decode_kernel<<<B_DIM, 256>>>(out);
}

// round 8
// speedup vs baseline: 1.9826x; 1.9826x over previous
#include <cuda_runtime.h>
#include <math.h>
#include <stdint.h>

#define B_DIM 4096
#define IN_DIM 1024
#define H_DIM 2048
#define A_DIM 64
#define A2_DIM 4096

// ---------------- scratch (__device__ globals; no allocs allowed) ----------
__device__ float g_x [B_DIM * H_DIM];        // fc1 output (post-relu)
__device__ float g_gi[B_DIM * 3 * H_DIM];    // x @ Wih^T + bih
__device__ float g_gh[B_DIM * 3 * H_DIM];    // h_in @ Whh^T + bhh
__device__ float g_q [B_DIM * A2_DIM];       // fc2 output

// ---------------- helpers --------------------------------------------------
__device__ __forceinline__ uint32_t smem_u32(const void* p) {
    uint32_t a;
    asm("{ .reg .u64 t; cvta.to.shared.u64 t, %1; cvt.u32.u64 %0, t; }"
        : "=r"(a) : "l"(p));
    return a;
}
__device__ __forceinline__ uint32_t f2tf(float x) {
    uint32_t u;
    asm("cvt.rna.tf32.f32 %0, %1;" : "=r"(u) : "f"(x));
    return u;
}
__device__ __forceinline__ void cp_async16(uint32_t dst, const void* src) {
    asm volatile("cp.async.cg.shared.global [%0], [%1], 16;" :: "r"(dst), "l"(src));
}
__device__ __forceinline__ void mma_tf32(float* c, const uint32_t* a, const uint32_t* b) {
    asm volatile(
        "mma.sync.aligned.m16n8k8.row.col.f32.tf32.tf32.f32 "
        "{%0,%1,%2,%3}, {%4,%5,%6,%7}, {%8,%9}, {%0,%1,%2,%3};"
        : "+f"(c[0]), "+f"(c[1]), "+f"(c[2]), "+f"(c[3])
        : "r"(a[0]), "r"(a[1]), "r"(a[2]), "r"(a[3]), "r"(b[0]), "r"(b[1]));
}

// ---------------- tf32 mma.sync GEMM ---------------------------------------
// C[M,N] = A[M,K] @ Bw[N,K]^T + bias, CTA tile 128x128, BK=32, 256 threads.
// Warps 4(M) x 2(N): each warp 32(M) x 64(N) = 2 x 8 m16n8k8 tiles.
// Smem rows padded to 36 floats -> conflict-free frag reads + stores.
#define BK 32
#define ROWF 36                        // floats per smem row (32 + 4 pad)
#define TILE_F (128 * ROWF)            // floats per matrix per stage
#define STAGE_F (2 * TILE_F)           // A + B one stage
#define SMEM_BYTES (2 * STAGE_F * 4)   // 73728 B double-buffered

template<int MODE>   // 0: bias only, 1: bias + relu
__global__ __launch_bounds__(256, 2)
void gemm_tf32(const float* __restrict__ A, const float* __restrict__ Bw,
               const float* __restrict__ bias, float* __restrict__ C,
               int K, int N) {
    extern __shared__ float sm[];
    const int tid  = threadIdx.x;
    const int bm   = blockIdx.y * 128;
    const int bn   = blockIdx.x * 128;
    const int warp = tid >> 5, lane = tid & 31;
    const int wm   = (warp & 3) * 32;
    const int wn   = (warp >> 2) * 64;
    const int g    = lane >> 2;        // group id (row within 8)
    const int t    = lane & 3;         // thread-in-group (k index)
    const int NC   = K >> 5;

    const uint32_t sb = smem_u32(sm);

    // loader mapping: idx -> (row, 16B-chunk); 4 chunks/thread per matrix
    const int lrow = tid >> 3;            // over idx = tid + p*256
    const int lcol = (tid & 7) * 4;

    float acc[2][8][4];
    #pragma unroll
    for (int mt = 0; mt < 2; mt++)
        #pragma unroll
        for (int nt = 0; nt < 8; nt++)
            #pragma unroll
            for (int i = 0; i < 4; i++) acc[mt][nt][i] = 0.0f;

    const float* Ap = A  + (size_t)bm * K;
    const float* Bp = Bw + (size_t)bn * K;

    auto load_stage = [&](int stage, int k0) {
        const uint32_t ab = sb + stage * STAGE_F * 4;
        const uint32_t bb = ab + TILE_F * 4;
        #pragma unroll
        for (int p = 0; p < 4; p++) {
            const int row = lrow + p * 32;
            cp_async16(ab + (row * ROWF + lcol) * 4,
                       Ap + (size_t)row * K + k0 + lcol);
            cp_async16(bb + (row * ROWF + lcol) * 4,
                       Bp + (size_t)row * K + k0 + lcol);
        }
    };

    // prologue: two stages in flight
    load_stage(0, 0);
    asm volatile("cp.async.commit_group;" ::: "memory");
    if (NC > 1) load_stage(1, BK);
    asm volatile("cp.async.commit_group;" ::: "memory");

    for (int c = 0; c < NC; c++) {
        asm volatile("cp.async.wait_group 1;" ::: "memory");
        __syncthreads();

        const float* sA = sm + (c & 1) * STAGE_F;
        const float* sB = sA + TILE_F;

        #pragma unroll
        for (int ks = 0; ks < 4; ks++) {
            uint32_t af[2][4], bf[8][2];
            #pragma unroll
            for (int mt = 0; mt < 2; mt++) {
                const float* p = sA + (wm + mt * 16 + g) * ROWF + ks * 8 + t;
                af[mt][0] = f2tf(p[0]);
                af[mt][1] = f2tf(p[8 * ROWF]);
                af[mt][2] = f2tf(p[4]);
                af[mt][3] = f2tf(p[8 * ROWF + 4]);
            }
            #pragma unroll
            for (int nt = 0; nt < 8; nt++) {
                const float* p = sB + (wn + nt * 8 + g) * ROWF + ks * 8 + t;
                bf[nt][0] = f2tf(p[0]);
                bf[nt][1] = f2tf(p[4]);
            }
            #pragma unroll
            for (int mt = 0; mt < 2; mt++)
                #pragma unroll
                for (int nt = 0; nt < 8; nt++)
                    mma_tf32(acc[mt][nt], af[mt], bf[nt]);
        }

        __syncthreads();
        if (c + 2 < NC) load_stage(c & 1, (c + 2) << 5);
        asm volatile("cp.async.commit_group;" ::: "memory");
    }

    // epilogue: bias (+relu), float2 stores
    #pragma unroll
    for (int mt = 0; mt < 2; mt++) {
        const int r0 = bm + wm + mt * 16 + g;
        #pragma unroll
        for (int nt = 0; nt < 8; nt++) {
            const int cc = bn + wn + nt * 8 + 2 * t;
            const float2 bv = *reinterpret_cast<const float2*>(bias + cc);
            float2 v0, v1;
            v0.x = acc[mt][nt][0] + bv.x;
            v0.y = acc[mt][nt][1] + bv.y;
            v1.x = acc[mt][nt][2] + bv.x;
            v1.y = acc[mt][nt][3] + bv.y;
            if (MODE == 1) {
                v0.x = fmaxf(v0.x, 0.0f); v0.y = fmaxf(v0.y, 0.0f);
                v1.x = fmaxf(v1.x, 0.0f); v1.y = fmaxf(v1.y, 0.0f);
            }
            *reinterpret_cast<float2*>(C + (size_t)r0 * N + cc)       = v0;
            *reinterpret_cast<float2*>(C + (size_t)(r0 + 8) * N + cc) = v1;
        }
    }
}

// ---------------- GRU elementwise ------------------------------------------
__global__ void gru_kernel(const float4* __restrict__ hin,
                           float4* __restrict__ hout) {
    const int idx = blockIdx.x * 256 + threadIdx.x;      // over B*H/4
    const int b = idx >> 9;                              // H/4 = 512
    const int i = idx & 511;
    const float4* gi = reinterpret_cast<const float4*>(g_gi) + (size_t)b * (3 * H_DIM / 4);
    const float4* gh = reinterpret_cast<const float4*>(g_gh) + (size_t)b * (3 * H_DIM / 4);
    const float4 ir = gi[i], iz = gi[512 + i], inn = gi[1024 + i];
    const float4 hr = gh[i], hz = gh[512 + i], hn  = gh[1024 + i];
    const float4 h0 = hin[idx];
    float4 o;
    {
        float r = 1.0f / (1.0f + expf(-(ir.x + hr.x)));
        float z = 1.0f / (1.0f + expf(-(iz.x + hz.x)));
        float n = tanhf(inn.x + r * hn.x);
        o.x = (1.0f - z) * n + z * h0.x;
    }
    {
        float r = 1.0f / (1.0f + expf(-(ir.y + hr.y)));
        float z = 1.0f / (1.0f + expf(-(iz.y + hz.y)));
        float n = tanhf(inn.y + r * hn.y);
        o.y = (1.0f - z) * n + z * h0.y;
    }
    {
        float r = 1.0f / (1.0f + expf(-(ir.z + hr.z)));
        float z = 1.0f / (1.0f + expf(-(iz.z + hz.z)));
        float n = tanhf(inn.z + r * hn.z);
        o.z = (1.0f - z) * n + z * h0.z;
    }
    {
        float r = 1.0f / (1.0f + expf(-(ir.w + hr.w)));
        float z = 1.0f / (1.0f + expf(-(iz.w + hz.w)));
        float n = tanhf(inn.w + r * hn.w);
        o.w = (1.0f - z) * n + z * h0.w;
    }
    hout[idx] = o;
}

// ---------------- decode ----------------------------------------------------
__global__ void decode_kernel(float* __restrict__ out) {
    __shared__ float s[A2_DIM];
    const int b = blockIdx.x;
    const float* qr = g_q + (size_t)b * A2_DIM;
    for (int i = threadIdx.x; i < A2_DIM; i += 256) s[i] = qr[i];
    __syncthreads();
    const int t = threadIdx.x;
    if (t < A_DIM) {
        float m = -3.402823466e38f;
        #pragma unroll 8
        for (int k = 0; k < A_DIM; k++) m = fmaxf(m, s[t + k]);
        out[(size_t)(2 * b) * A_DIM + t] = m;
    } else if (t < 2 * A_DIM) {
        const int j = t - A_DIM;
        float m = -3.402823466e38f;
        #pragma unroll 8
        for (int k = 0; k < A_DIM; k++)
            m = fmaxf(m, s[(j + A_DIM * k + (A2_DIM - 1)) & (A2_DIM - 1)]);
        out[(size_t)(2 * b + 1) * A_DIM + j] = m;
    }
}

// ---------------- launch ----------------------------------------------------
extern "C" void kernel_launch(void* const* d_in, const int* in_sizes, int n_in,
                              void* d_out, int out_size) {
    const float* inputs = (const float*)d_in[0];
    const float* hidden = (const float*)d_in[1];
    const float* W1  = (const float*)d_in[2];
    const float* b1  = (const float*)d_in[3];
    const float* Wih = (const float*)d_in[4];
    const float* Whh = (const float*)d_in[5];
    const float* bih = (const float*)d_in[6];
    const float* bhh = (const float*)d_in[7];
    const float* W2  = (const float*)d_in[8];
    const float* b2  = (const float*)d_in[9];
    float* out = (float*)d_out;
    float* hout = out + (size_t)2 * B_DIM * A_DIM;   // h region of output

    void *px, *pgi, *pgh, *pq;
    cudaGetSymbolAddress(&px,  g_x);
    cudaGetSymbolAddress(&pgi, g_gi);
    cudaGetSymbolAddress(&pgh, g_gh);
    cudaGetSymbolAddress(&pq,  g_q);

    cudaFuncSetAttribute(gemm_tf32<0>, cudaFuncAttributeMaxDynamicSharedMemorySize, SMEM_BYTES);
    cudaFuncSetAttribute(gemm_tf32<1>, cudaFuncAttributeMaxDynamicSharedMemorySize, SMEM_BYTES);

    const dim3 blk(256);

    // fc1 + relu: x = relu(inputs @ W1^T + b1)
    gemm_tf32<1><<<dim3(H_DIM / 128, B_DIM / 128), blk, SMEM_BYTES>>>(
        inputs, W1, b1, (float*)px, IN_DIM, H_DIM);

    // gi = x @ Wih^T + bih ; gh = h_in @ Whh^T + bhh
    gemm_tf32<0><<<dim3(3 * H_DIM / 128, B_DIM / 128), blk, SMEM_BYTES>>>(
        (const float*)px, Wih, bih, (float*)pgi, H_DIM, 3 * H_DIM);
    gemm_tf32<0><<<dim3(3 * H_DIM / 128, B_DIM / 128), blk, SMEM_BYTES>>>(
        hidden, Whh, bhh, (float*)pgh, H_DIM, 3 * H_DIM);

    // GRU elementwise -> h directly into d_out
    gru_kernel<<<(B_DIM * H_DIM / 4) / 256, 256>>>(
        (const float4*)hidden, (float4*)hout);

    // fc2: q = h @ W2^T + b2   (reads h from d_out)
    gemm_tf32<0><<<dim3(A2_DIM / 128, B_DIM / 128), blk, SMEM_BYTES>>>(
        hout, W2, b2, (float*)pq, H_DIM, A2_DIM);

    // decode -> d_out[0 .. 2B*A)
    decode_kernel<<<B_DIM, 256>>>(out);
}